// round 10
// baseline (speedup 1.0000x reference)
#include <cuda_runtime.h>
#include <cuda_fp16.h>
#include <math.h>

#define HF 200
#define WF 200
#define CH 256
#define HO 7
#define WO 7
#define SUBS 2
#define HS (HO * SUBS)   // 14
#define WS (WO * SUBS)   // 14

#define ROW_BYTES (WF * CH * 2)   // 102400
#define COL_BYTES (CH * 2)        // 512
#define SPITCH 264                // halves per staged position (256 + 8 pad)
#define NTHR 224
#define DEPTH 3
#define STAGE_BYTES (16 * NTHR * 16)           // 57344 per pipeline stage
#define RES_OFF (DEPTH * STAGE_BYTES)          // 172032
#define SMEM_BYTES (RES_OFF + WO * SPITCH * 2) // 175728

#define NBLK 128                  // 3584 units = 128 * 28 exactly
#define UNITS_PER_BLK 28

// Channels-last fp16 scratch copy: g_featTh[(y*WF + x)*CH + c]  (20.5 MB)
__device__ __align__(16) __half g_featTh[HF * WF * CH];

static __device__ __forceinline__ __half2 u2h2(unsigned u) {
    return *reinterpret_cast<__half2*>(&u);
}
static __device__ __forceinline__ void cp_async16(unsigned dst_smem, const void* src) {
    asm volatile("cp.async.cg.shared.global [%0], [%1], 16;\n"
                 :: "r"(dst_smem), "l"(src) : "memory");
}
static __device__ __forceinline__ void cp_commit() {
    asm volatile("cp.async.commit_group;\n" ::: "memory");
}
static __device__ __forceinline__ void cp_wait2() {
    asm volatile("cp.async.wait_group 2;\n" ::: "memory");
}

// ---------------------------------------------------------------------------
// Kernel 1: transpose (C, H*W) f32 -> (H*W, C) fp16 (HBM-roofline bound)
// ---------------------------------------------------------------------------
__global__ void transpose_kernel(const float* __restrict__ in) {
    __shared__ float tile[32][33];
    const int p0 = blockIdx.x * 32;
    const int c0 = blockIdx.y * 32;
    const int tx = threadIdx.x;
    const int ty = threadIdx.y;

#pragma unroll
    for (int i = 0; i < 32; i += 8) {
        tile[ty + i][tx] = in[(size_t)(c0 + ty + i) * (HF * WF) + (p0 + tx)];
    }
    __syncthreads();

    const int tid = ty * 32 + tx;
#pragma unroll
    for (int it = 0; it < 2; it++) {
        const int idx = tid + it * 256;
        const int p_local = idx >> 4;
        const int k = idx & 15;
        __half2 h = __floats2half2_rn(tile[2 * k][p_local], tile[2 * k + 1][p_local]);
        *(__half2*)&g_featTh[(size_t)(p0 + p_local) * CH + c0 + 2 * k] = h;
    }
}

// ---------------------------------------------------------------------------
// Kernel 2: persistent ROI align, 3-deep cp.async pipeline.
// Grid: 128 blocks x 224 threads; block b owns units [b*28, b*28+28),
// unit u -> (n = u/7, ph = u%7). Thread = (pw = tid>>5, c8 = tid&31).
// Pipeline: issue tile i+2 -> wait_group 2 (tile i landed) -> compute tile i.
// Threads read only their own staged slots: no sync on corner data.
// ---------------------------------------------------------------------------
struct Geom {
    unsigned offs[16];
    __half2 fx0, fx1, fy0, fy1;
};

static __device__ __forceinline__ void unit_geometry(
    const float4* __restrict__ rois4, const float Hi, const float Wi,
    int u, int pw, Geom& g)
{
    const int n  = u / 7;
    const int ph = u - n * 7;

    const float4 roi = __ldg(rois4 + n);
    const float sy_scale = (HF - 1.0f) / (Hi - 1.0f);
    const float sx_scale = (WF - 1.0f) / (Wi - 1.0f);
    const float r0 = roi.x * sy_scale;
    const float r1 = roi.y * sx_scale;
    const float h_step = (roi.z * sy_scale - r0) * (1.0f / (float)HS);
    const float w_step = (roi.w * sx_scale - r1) * (1.0f / (float)WS);

    const float yy0 = ((float)(2 * ph) + 0.5f) * h_step + r0;
    const float yy1 = yy0 + h_step;
    const float xx0 = ((float)(2 * pw) + 0.5f) * w_step + r1;
    const float xx1 = xx0 + w_step;

    const int iy0 = __float2int_rd(yy0);
    const int iy1 = __float2int_rd(yy1);
    const int ix0 = __float2int_rd(xx0);
    const int ix1 = __float2int_rd(xx1);

    g.fy0 = __float2half2_rn(yy0 - (float)iy0);
    g.fy1 = __float2half2_rn(yy1 - (float)iy1);
    g.fx0 = __float2half2_rn(xx0 - (float)ix0);
    g.fx1 = __float2half2_rn(xx1 - (float)ix1);

    const unsigned ru0 = (unsigned)iy0 * ROW_BYTES;
    const unsigned ru1 = (unsigned)iy1 * ROW_BYTES;
    const unsigned rd0 = ru0 + ROW_BYTES;
    const unsigned rd1 = ru1 + ROW_BYTES;
    const unsigned cl0 = (unsigned)ix0 * COL_BYTES;
    const unsigned cl1 = (unsigned)ix1 * COL_BYTES;
    const unsigned cr0 = cl0 + COL_BYTES;
    const unsigned cr1 = cl1 + COL_BYTES;

    g.offs[ 0] = ru0 + cl0;  g.offs[ 1] = ru0 + cr0;
    g.offs[ 2] = rd0 + cl0;  g.offs[ 3] = rd0 + cr0;
    g.offs[ 4] = ru0 + cl1;  g.offs[ 5] = ru0 + cr1;
    g.offs[ 6] = rd0 + cl1;  g.offs[ 7] = rd0 + cr1;
    g.offs[ 8] = ru1 + cl0;  g.offs[ 9] = ru1 + cr0;
    g.offs[10] = rd1 + cl0;  g.offs[11] = rd1 + cr0;
    g.offs[12] = ru1 + cl1;  g.offs[13] = ru1 + cr1;
    g.offs[14] = rd1 + cl1;  g.offs[15] = rd1 + cr1;
}

__global__ __launch_bounds__(NTHR) void roialign_kernel(
    const float* __restrict__ rois,
    const float* __restrict__ img_size,
    float* __restrict__ out)
{
    extern __shared__ __align__(16) unsigned char dsmem[];
    const uint4* stage = (const uint4*)dsmem;
    __half* s_half = (__half*)(dsmem + RES_OFF);
    const unsigned sbase = (unsigned)__cvta_generic_to_shared(dsmem);

    const int tid = threadIdx.x;
    const int pw  = tid >> 5;
    const int c8  = tid & 31;
    const int u0  = blockIdx.x * UNITS_PER_BLK;

    const float4* rois4 = (const float4*)rois;
    const float Hi = __ldg(img_size);
    const float Wi = __ldg(img_size + 1);
    const char* fb = (const char*)g_featTh + c8 * 16;

    // --- prologue: issue tiles 0, 1 ---
#pragma unroll
    for (int p = 0; p < DEPTH - 1; p++) {
        Geom g;
        unit_geometry(rois4, Hi, Wi, u0 + p, pw, g);
        const unsigned dbase = sbase + (unsigned)(p * STAGE_BYTES) + (unsigned)tid * 16u;
#pragma unroll
        for (int i = 0; i < 16; i++) {
            cp_async16(dbase + (unsigned)i * (NTHR * 16u), fb + g.offs[i]);
        }
        cp_commit();
    }

    // --- main loop over 28 tiles ---
    for (int it = 0; it < UNITS_PER_BLK; it++) {
        // issue tile it+2 (or an empty group to keep the count aligned)
        if (it + DEPTH - 1 < UNITS_PER_BLK) {
            const int p = (it + DEPTH - 1) % DEPTH;
            Geom g;
            unit_geometry(rois4, Hi, Wi, u0 + it + DEPTH - 1, pw, g);
            const unsigned dbase = sbase + (unsigned)(p * STAGE_BYTES) + (unsigned)tid * 16u;
#pragma unroll
            for (int i = 0; i < 16; i++) {
                cp_async16(dbase + (unsigned)i * (NTHR * 16u), fb + g.offs[i]);
            }
        }
        cp_commit();
        cp_wait2();   // tile `it` has landed

        // recompute fractions for tile `it` (cheap, bitwise-identical)
        Geom g;
        unit_geometry(rois4, Hi, Wi, u0 + it, pw, g);

        const uint4* buf = stage + (size_t)(it % DEPTH) * (STAGE_BYTES / 16);

        __half2 best[4];
        const __half2 ninf = __float2half2_rn(-60000.0f);
#pragma unroll
        for (int j = 0; j < 4; j++) best[j] = ninf;

        const __half2 fxs[4] = {g.fx0, g.fx1, g.fx0, g.fx1};
        const __half2 fys[4] = {g.fy0, g.fy0, g.fy1, g.fy1};

#pragma unroll
        for (int s = 0; s < 4; s++) {
            const uint4 vul = buf[(s * 4 + 0) * NTHR + tid];
            const uint4 vur = buf[(s * 4 + 1) * NTHR + tid];
            const uint4 vdl = buf[(s * 4 + 2) * NTHR + tid];
            const uint4 vdr = buf[(s * 4 + 3) * NTHR + tid];
            const unsigned* pul = (const unsigned*)&vul;
            const unsigned* pur = (const unsigned*)&vur;
            const unsigned* pdl = (const unsigned*)&vdl;
            const unsigned* pdr = (const unsigned*)&vdr;
            const __half2 fx2 = fxs[s];
            const __half2 fy2 = fys[s];
#pragma unroll
            for (int j = 0; j < 4; j++) {
                const __half2 ul = u2h2(pul[j]);
                const __half2 ur = u2h2(pur[j]);
                const __half2 dl = u2h2(pdl[j]);
                const __half2 dr = u2h2(pdr[j]);
                const __half2 t = __hfma2(fx2, __hsub2(ur, ul), ul);
                const __half2 b = __hfma2(fx2, __hsub2(dr, dl), dl);
                const __half2 vv = __hfma2(fy2, __hsub2(b, t), t);
                best[j] = __hmax2(best[j], vv);
            }
        }

        // stage + coalesced writeback for this tile
        *(uint4*)&s_half[pw * SPITCH + c8 * 8] = *(const uint4*)best;
        __syncthreads();
        {
            const int u  = u0 + it;
            const int n  = u / 7;
            const int ph = u - n * 7;
            int c  = tid / 7;
            const int wpw = tid - c * 7;
            const __half* sp = s_half + wpw * SPITCH;
            float* gp = out + (size_t)n * (CH * HO * WO) + (size_t)c * (HO * WO)
                            + ph * WO + wpw;
#pragma unroll
            for (int k = 0; k < 8; k++) {
                *gp = __half2float(sp[c]);
                c  += 32;
                gp += 32 * (HO * WO);
            }
        }
        __syncthreads();
    }
}

extern "C" void kernel_launch(void* const* d_in, const int* in_sizes, int n_in,
                              void* d_out, int out_size) {
    const float* features = (const float*)d_in[0];  // (1, 256, 200, 200)
    const float* rois     = (const float*)d_in[1];  // (512, 4)
    const float* img_size = (const float*)d_in[2];  // (2,)
    float* out = (float*)d_out;                     // (512, 256, 7, 7)

    static int attr_set = 0;
    if (!attr_set) {
        cudaFuncSetAttribute(roialign_kernel,
                             cudaFuncAttributeMaxDynamicSharedMemorySize,
                             SMEM_BYTES);
        attr_set = 1;
    }

    dim3 tgrid(HF * WF / 32, CH / 32);
    dim3 tblock(32, 8);
    transpose_kernel<<<tgrid, tblock>>>(features);

    roialign_kernel<<<NBLK, NTHR, SMEM_BYTES>>>(rois, img_size, out);
}

// round 11
// speedup vs baseline: 1.3039x; 1.3039x over previous
#include <cuda_runtime.h>
#include <cuda_fp16.h>
#include <math.h>

#define HF 200
#define WF 200
#define CH 256
#define HO 7
#define WO 7
#define SUBS 2
#define HS (HO * SUBS)   // 14
#define WS (WO * SUBS)   // 14

#define ROW_BYTES (WF * CH * 2)   // 102400
#define COL_BYTES (CH * 2)        // 512
#define SPITCH 264                // halves per staged position (256 + 8 pad)
#define NTHR 224
#define SMEM_BYTES (16 * NTHR * 16)   // 57344: stage[16][224] of uint4

// Channels-last fp16 scratch copy: g_featTh[(y*WF + x)*CH + c]  (20.5 MB)
__device__ __align__(16) __half g_featTh[HF * WF * CH];

static __device__ __forceinline__ __half2 u2h2(unsigned u) {
    return *reinterpret_cast<__half2*>(&u);
}
static __device__ __forceinline__ void cp_async16(unsigned dst_smem, const void* src) {
    asm volatile("cp.async.cg.shared.global [%0], [%1], 16;\n"
                 :: "r"(dst_smem), "l"(src) : "memory");
}
static __device__ __forceinline__ void cp_commit() {
    asm volatile("cp.async.commit_group;\n" ::: "memory");
}

// ---------------------------------------------------------------------------
// Kernel 1: transpose (C, H*W) f32 -> (H*W, C) fp16 (HBM-roofline bound)
// ---------------------------------------------------------------------------
__global__ void transpose_kernel(const float* __restrict__ in) {
    __shared__ float tile[32][33];
    const int p0 = blockIdx.x * 32;
    const int c0 = blockIdx.y * 32;
    const int tx = threadIdx.x;
    const int ty = threadIdx.y;

#pragma unroll
    for (int i = 0; i < 32; i += 8) {
        tile[ty + i][tx] = in[(size_t)(c0 + ty + i) * (HF * WF) + (p0 + tx)];
    }
    __syncthreads();

    const int tid = ty * 32 + tx;
#pragma unroll
    for (int it = 0; it < 2; it++) {
        const int idx = tid + it * 256;
        const int p_local = idx >> 4;
        const int k = idx & 15;
        __half2 h = __floats2half2_rn(tile[2 * k][p_local], tile[2 * k + 1][p_local]);
        *(__half2*)&g_featTh[(size_t)(p0 + p_local) * CH + c0 + 2 * k] = h;
    }
}

// ---------------------------------------------------------------------------
// Kernel 2: ROI align + 2x2 max subsample via cp.async, 4 commit groups.
// Grid: (N, 7). Block: 224 threads = 7 pw x 32 c8 (one-shot, 3 blocks/SM).
// Loads split into 4 groups (one bilinear sample = 4 corners each);
// compute of sample s overlaps delivery of samples s+1..3.
// ---------------------------------------------------------------------------
__global__ __launch_bounds__(NTHR) void roialign_kernel(
    const float* __restrict__ rois,
    const float* __restrict__ img_size,
    float* __restrict__ out)
{
    extern __shared__ __align__(16) unsigned char dsmem[];
    const uint4* stage = (const uint4*)dsmem;
    const unsigned sbase = (unsigned)__cvta_generic_to_shared(dsmem);

    const int n   = blockIdx.x;
    const int ph  = blockIdx.y;
    const int tid = threadIdx.x;
    const int pw  = tid >> 5;     // 0..6
    const int c8  = tid & 31;     // 0..31

    const float4 roi = __ldg((const float4*)rois + n);
    const float Hi = __ldg(img_size);
    const float Wi = __ldg(img_size + 1);
    const float sy_scale = (HF - 1.0f) / (Hi - 1.0f);
    const float sx_scale = (WF - 1.0f) / (Wi - 1.0f);
    const float r0 = roi.x * sy_scale;
    const float r1 = roi.y * sx_scale;
    const float h_step = (roi.z * sy_scale - r0) * (1.0f / (float)HS);
    const float w_step = (roi.w * sx_scale - r1) * (1.0f / (float)WS);

    // --- per-thread geometry ---
    const float yy0 = ((float)(2 * ph) + 0.5f) * h_step + r0;
    const float yy1 = yy0 + h_step;
    const float xx0 = ((float)(2 * pw) + 0.5f) * w_step + r1;
    const float xx1 = xx0 + w_step;

    const int iy0 = __float2int_rd(yy0);
    const int iy1 = __float2int_rd(yy1);
    const int ix0 = __float2int_rd(xx0);
    const int ix1 = __float2int_rd(xx1);

    const __half2 fy0 = __float2half2_rn(yy0 - (float)iy0);
    const __half2 fy1 = __float2half2_rn(yy1 - (float)iy1);
    const __half2 fx0 = __float2half2_rn(xx0 - (float)ix0);
    const __half2 fx1 = __float2half2_rn(xx1 - (float)ix1);

    const unsigned ru0 = (unsigned)iy0 * ROW_BYTES;
    const unsigned ru1 = (unsigned)iy1 * ROW_BYTES;
    const unsigned rd0 = ru0 + ROW_BYTES;
    const unsigned rd1 = ru1 + ROW_BYTES;
    const unsigned cl0 = (unsigned)ix0 * COL_BYTES;
    const unsigned cl1 = (unsigned)ix1 * COL_BYTES;
    const unsigned cr0 = cl0 + COL_BYTES;
    const unsigned cr1 = cl1 + COL_BYTES;

    const char* fb = (const char*)g_featTh + c8 * 16;

    // --- issue 4 groups: one bilinear sample (4 corners) per group ---
    const unsigned offs[16] = {
        ru0 + cl0, ru0 + cr0, rd0 + cl0, rd0 + cr0,   // sample 0: (sy0, sx0)
        ru0 + cl1, ru0 + cr1, rd0 + cl1, rd0 + cr1,   // sample 1: (sy0, sx1)
        ru1 + cl0, ru1 + cr0, rd1 + cl0, rd1 + cr0,   // sample 2: (sy1, sx0)
        ru1 + cl1, ru1 + cr1, rd1 + cl1, rd1 + cr1    // sample 3: (sy1, sx1)
    };
    const unsigned dbase = sbase + (unsigned)tid * 16u;
#pragma unroll
    for (int s = 0; s < 4; s++) {
#pragma unroll
        for (int i = 0; i < 4; i++) {
            const int slot = s * 4 + i;
            cp_async16(dbase + (unsigned)slot * (NTHR * 16u), fb + offs[slot]);
        }
        cp_commit();
    }

    // writeback indices: compute now (latency-free slot before the waits)
    int wc = tid / 7;
    const int wpw = tid - wc * 7;
    float* gp = out + (size_t)n * (CH * HO * WO) + (size_t)wc * (HO * WO)
                    + ph * WO + wpw;

    // --- progressive consume: wait_group (3-s) -> compute sample s ---
    __half2 best[4];
    const __half2 ninf = __float2half2_rn(-60000.0f);
#pragma unroll
    for (int j = 0; j < 4; j++) best[j] = ninf;

    const __half2 fxs[4] = {fx0, fx1, fx0, fx1};
    const __half2 fys[4] = {fy0, fy0, fy1, fy1};

#pragma unroll
    for (int s = 0; s < 4; s++) {
        switch (s) {
            case 0: asm volatile("cp.async.wait_group 3;\n" ::: "memory"); break;
            case 1: asm volatile("cp.async.wait_group 2;\n" ::: "memory"); break;
            case 2: asm volatile("cp.async.wait_group 1;\n" ::: "memory"); break;
            default: asm volatile("cp.async.wait_group 0;\n" ::: "memory"); break;
        }
        const uint4 vul = stage[(s * 4 + 0) * NTHR + tid];
        const uint4 vur = stage[(s * 4 + 1) * NTHR + tid];
        const uint4 vdl = stage[(s * 4 + 2) * NTHR + tid];
        const uint4 vdr = stage[(s * 4 + 3) * NTHR + tid];
        const unsigned* pul = (const unsigned*)&vul;
        const unsigned* pur = (const unsigned*)&vur;
        const unsigned* pdl = (const unsigned*)&vdl;
        const unsigned* pdr = (const unsigned*)&vdr;
        const __half2 fx2 = fxs[s];
        const __half2 fy2 = fys[s];
#pragma unroll
        for (int j = 0; j < 4; j++) {
            const __half2 ul = u2h2(pul[j]);
            const __half2 ur = u2h2(pur[j]);
            const __half2 dl = u2h2(pdl[j]);
            const __half2 dr = u2h2(pdr[j]);
            const __half2 t = __hfma2(fx2, __hsub2(ur, ul), ul);
            const __half2 b = __hfma2(fx2, __hsub2(dr, dl), dl);
            const __half2 vv = __hfma2(fy2, __hsub2(b, t), t);
            best[j] = __hmax2(best[j], vv);
        }
    }

    // --- stage results (reuse smem; all corner reads are done) ---
    __syncthreads();
    __half* s_half = (__half*)dsmem;
    *(uint4*)&s_half[pw * SPITCH + c8 * 8] = *(const uint4*)best;
    __syncthreads();

    // --- writeback: fixed pw per thread, c += 32 per iter ---
    {
        const __half* sp = s_half + wpw * SPITCH;
#pragma unroll
        for (int k = 0; k < 8; k++) {
            *gp = __half2float(sp[wc]);
            wc += 32;
            gp += 32 * (HO * WO);
        }
    }
}

extern "C" void kernel_launch(void* const* d_in, const int* in_sizes, int n_in,
                              void* d_out, int out_size) {
    const float* features = (const float*)d_in[0];  // (1, 256, 200, 200)
    const float* rois     = (const float*)d_in[1];  // (512, 4)
    const float* img_size = (const float*)d_in[2];  // (2,)
    float* out = (float*)d_out;                     // (512, 256, 7, 7)

    const int n_rois = in_sizes[1] / 4;

    static int attr_set = 0;
    if (!attr_set) {
        cudaFuncSetAttribute(roialign_kernel,
                             cudaFuncAttributeMaxDynamicSharedMemorySize,
                             SMEM_BYTES);
        attr_set = 1;
    }

    dim3 tgrid(HF * WF / 32, CH / 32);
    dim3 tblock(32, 8);
    transpose_kernel<<<tgrid, tblock>>>(features);

    dim3 rgrid(n_rois, HO);
    roialign_kernel<<<rgrid, NTHR, SMEM_BYTES>>>(rois, img_size, out);
}

// round 12
// speedup vs baseline: 1.3052x; 1.0010x over previous
#include <cuda_runtime.h>
#include <cuda_fp16.h>
#include <math.h>

#define HF 200
#define WF 200
#define CH 256
#define HO 7
#define WO 7
#define SUBS 2
#define HS (HO * SUBS)   // 14
#define WS (WO * SUBS)   // 14

#define ROW_BYTES (WF * CH * 2)   // 102400
#define COL_BYTES (CH * 2)        // 512
#define SPITCH 264                // halves per staged position (256 + 8 pad)
#define NTHR 224

// Channels-last fp16 scratch copy: g_featTh[(y*WF + x)*CH + c]  (20.5 MB)
__device__ __align__(16) __half g_featTh[HF * WF * CH];

static __device__ __forceinline__ __half2 u2h2(unsigned u) {
    return *reinterpret_cast<__half2*>(&u);
}

// Forced LDG.128: asm volatile outputs cannot be register-reused by ptxas,
// so 16 of these in a row issue back-to-back (MLP = 16 guaranteed).
#define LDG128_NC(r, p)                                                        \
    asm volatile("ld.global.nc.v4.u32 {%0,%1,%2,%3}, [%4];"                    \
                 : "=r"((r)[0]), "=r"((r)[1]), "=r"((r)[2]), "=r"((r)[3])      \
                 : "l"(p))

// ---------------------------------------------------------------------------
// Kernel 1: transpose (C, H*W) f32 -> (H*W, C) fp16 (HBM-roofline bound)
// ---------------------------------------------------------------------------
__global__ void transpose_kernel(const float* __restrict__ in) {
    __shared__ float tile[32][33];
    const int p0 = blockIdx.x * 32;
    const int c0 = blockIdx.y * 32;
    const int tx = threadIdx.x;
    const int ty = threadIdx.y;

#pragma unroll
    for (int i = 0; i < 32; i += 8) {
        tile[ty + i][tx] = in[(size_t)(c0 + ty + i) * (HF * WF) + (p0 + tx)];
    }
    __syncthreads();

    const int tid = ty * 32 + tx;
#pragma unroll
    for (int it = 0; it < 2; it++) {
        const int idx = tid + it * 256;
        const int p_local = idx >> 4;
        const int k = idx & 15;
        __half2 h = __floats2half2_rn(tile[2 * k][p_local], tile[2 * k + 1][p_local]);
        *(__half2*)&g_featTh[(size_t)(p0 + p_local) * CH + c0 + 2 * k] = h;
    }
}

// ---------------------------------------------------------------------------
// Kernel 2: ROI align + 2x2 max subsample, asm-forced LDG.128 batch.
// Grid: (N, 7). Block: 224 threads = 7 pw x 32 c8.
// All 16 corner loads issued via inline-asm LDG.128 into 64 live registers
// (ptxas cannot serialize), riding the 128 B/cyc/SM LDG path instead of
// cp.async's 64 B/cyc LDGSTS path. min 3 blocks/SM (reg cap 97).
// ---------------------------------------------------------------------------
__global__ __launch_bounds__(NTHR, 3) void roialign_kernel(
    const float* __restrict__ rois,
    const float* __restrict__ img_size,
    float* __restrict__ out)
{
    __shared__ __align__(16) __half s_half[WO * SPITCH];  // 3.7 KB

    const int n   = blockIdx.x;
    const int ph  = blockIdx.y;
    const int tid = threadIdx.x;
    const int pw  = tid >> 5;     // 0..6
    const int c8  = tid & 31;     // 0..31

    const float4 roi = __ldg((const float4*)rois + n);
    const float Hi = __ldg(img_size);
    const float Wi = __ldg(img_size + 1);
    const float sy_scale = (HF - 1.0f) / (Hi - 1.0f);
    const float sx_scale = (WF - 1.0f) / (Wi - 1.0f);
    const float r0 = roi.x * sy_scale;
    const float r1 = roi.y * sx_scale;
    const float h_step = (roi.z * sy_scale - r0) * (1.0f / (float)HS);
    const float w_step = (roi.w * sx_scale - r1) * (1.0f / (float)WS);

    // --- per-thread geometry ---
    const float yy0 = ((float)(2 * ph) + 0.5f) * h_step + r0;
    const float yy1 = yy0 + h_step;
    const float xx0 = ((float)(2 * pw) + 0.5f) * w_step + r1;
    const float xx1 = xx0 + w_step;

    const int iy0 = __float2int_rd(yy0);
    const int iy1 = __float2int_rd(yy1);
    const int ix0 = __float2int_rd(xx0);
    const int ix1 = __float2int_rd(xx1);

    const __half2 fy0 = __float2half2_rn(yy0 - (float)iy0);
    const __half2 fy1 = __float2half2_rn(yy1 - (float)iy1);
    const __half2 fx0 = __float2half2_rn(xx0 - (float)ix0);
    const __half2 fx1 = __float2half2_rn(xx1 - (float)ix1);

    // corner byte offsets (floor+1 trick: down/right = +stride, weight-0 safe)
    const unsigned ru0 = (unsigned)iy0 * ROW_BYTES;
    const unsigned ru1 = (unsigned)iy1 * ROW_BYTES;
    const unsigned rd0 = ru0 + ROW_BYTES;
    const unsigned rd1 = ru1 + ROW_BYTES;
    const unsigned cl0 = (unsigned)ix0 * COL_BYTES;
    const unsigned cl1 = (unsigned)ix1 * COL_BYTES;
    const unsigned cr0 = cl0 + COL_BYTES;
    const unsigned cr1 = cl1 + COL_BYTES;

    const char* fb = (const char*)g_featTh + c8 * 16;

    // --- 16 forced LDG.128s: 64 live registers, back-to-back issue ---
    unsigned v[64];
    LDG128_NC(v +  0, fb + (ru0 + cl0));   // s0 ul
    LDG128_NC(v +  4, fb + (ru0 + cr0));   // s0 ur
    LDG128_NC(v +  8, fb + (rd0 + cl0));   // s0 dl
    LDG128_NC(v + 12, fb + (rd0 + cr0));   // s0 dr
    LDG128_NC(v + 16, fb + (ru0 + cl1));   // s1 ul
    LDG128_NC(v + 20, fb + (ru0 + cr1));   // s1 ur
    LDG128_NC(v + 24, fb + (rd0 + cl1));   // s1 dl
    LDG128_NC(v + 28, fb + (rd0 + cr1));   // s1 dr
    LDG128_NC(v + 32, fb + (ru1 + cl0));   // s2 ul
    LDG128_NC(v + 36, fb + (ru1 + cr0));   // s2 ur
    LDG128_NC(v + 40, fb + (rd1 + cl0));   // s2 dl
    LDG128_NC(v + 44, fb + (rd1 + cr0));   // s2 dr
    LDG128_NC(v + 48, fb + (ru1 + cl1));   // s3 ul
    LDG128_NC(v + 52, fb + (ru1 + cr1));   // s3 ur
    LDG128_NC(v + 56, fb + (rd1 + cl1));   // s3 dl
    LDG128_NC(v + 60, fb + (rd1 + cr1));   // s3 dr

    __half2 best[4];
    const __half2 ninf = __float2half2_rn(-60000.0f);
#pragma unroll
    for (int j = 0; j < 4; j++) best[j] = ninf;

    const __half2 fxs[4] = {fx0, fx1, fx0, fx1};
    const __half2 fys[4] = {fy0, fy0, fy1, fy1};

#pragma unroll
    for (int s = 0; s < 4; s++) {
        const unsigned* pul = v + s * 16 + 0;
        const unsigned* pur = v + s * 16 + 4;
        const unsigned* pdl = v + s * 16 + 8;
        const unsigned* pdr = v + s * 16 + 12;
        const __half2 fx2 = fxs[s];
        const __half2 fy2 = fys[s];
#pragma unroll
        for (int j = 0; j < 4; j++) {
            const __half2 ul = u2h2(pul[j]);
            const __half2 ur = u2h2(pur[j]);
            const __half2 dl = u2h2(pdl[j]);
            const __half2 dr = u2h2(pdr[j]);
            const __half2 t = __hfma2(fx2, __hsub2(ur, ul), ul);
            const __half2 b = __hfma2(fx2, __hsub2(dr, dl), dl);
            const __half2 vv = __hfma2(fy2, __hsub2(b, t), t);
            best[j] = __hmax2(best[j], vv);
        }
    }

    // --- stage results in fp16 smem ---
    *(uint4*)&s_half[pw * SPITCH + c8 * 8] = *(const uint4*)best;
    __syncthreads();

    // --- writeback: fixed pw per thread, c += 32 per iter ---
    {
        int c  = tid / 7;
        const int wpw = tid - c * 7;
        const __half* sp = s_half + wpw * SPITCH;
        float* gp = out + (size_t)n * (CH * HO * WO) + (size_t)c * (HO * WO)
                        + ph * WO + wpw;
#pragma unroll
        for (int k = 0; k < 8; k++) {
            *gp = __half2float(sp[c]);
            c  += 32;
            gp += 32 * (HO * WO);
        }
    }
}

extern "C" void kernel_launch(void* const* d_in, const int* in_sizes, int n_in,
                              void* d_out, int out_size) {
    const float* features = (const float*)d_in[0];  // (1, 256, 200, 200)
    const float* rois     = (const float*)d_in[1];  // (512, 4)
    const float* img_size = (const float*)d_in[2];  // (2,)
    float* out = (float*)d_out;                     // (512, 256, 7, 7)

    const int n_rois = in_sizes[1] / 4;

    dim3 tgrid(HF * WF / 32, CH / 32);
    dim3 tblock(32, 8);
    transpose_kernel<<<tgrid, tblock>>>(features);

    dim3 rgrid(n_rois, HO);
    roialign_kernel<<<rgrid, NTHR>>>(rois, img_size, out);
}

// round 14
// speedup vs baseline: 1.3159x; 1.0082x over previous
#include <cuda_runtime.h>
#include <cuda_fp16.h>
#include <math.h>

#define HF 200
#define WF 200
#define CH 256
#define HO 7
#define WO 7
#define SUBS 2
#define HS (HO * SUBS)   // 14
#define WS (WO * SUBS)   // 14

#define ROW_BYTES (WF * CH * 2)   // 102400
#define COL_BYTES (CH * 2)        // 512
#define SPITCH 264                // halves per staged position (256 + 8 pad)
#define NTHR 224

// Channels-last fp16 scratch copy: g_featTh[(y*WF + x)*CH + c]  (20.5 MB)
__device__ __align__(1024) __half g_featTh[HF * WF * CH];

static __device__ __forceinline__ __half2 u2h2(unsigned u) {
    return *reinterpret_cast<__half2*>(&u);
}
static __device__ __forceinline__ unsigned long long evict_last_policy() {
    unsigned long long pol;
    asm("createpolicy.fractional.L2::evict_last.b64 %0, 1.0;" : "=l"(pol));
    return pol;
}

// Forced LDG.128 with L2 evict_last hint: asm outputs can't be register-reused
// by ptxas, so 16 in a row issue back-to-back (MLP = 16 guaranteed).
#define LDG128_NC_EL(r, p, pol)                                                \
    asm volatile("ld.global.nc.L2::cache_hint.v4.u32 {%0,%1,%2,%3}, [%4], %5;" \
                 : "=r"((r)[0]), "=r"((r)[1]), "=r"((r)[2]), "=r"((r)[3])      \
                 : "l"(p), "l"(pol))

// ---------------------------------------------------------------------------
// Kernel 1: transpose (C, H*W) f32 -> (H*W, C) fp16.
// featT stores carry evict_last so the 20.5 MB map stays L2-resident.
// Each block triggers PDL completion on entry so the dependent roialign
// launch can begin its prologue during the transpose tail wave.
// ---------------------------------------------------------------------------
__global__ void transpose_kernel(const float* __restrict__ in) {
    cudaTriggerProgrammaticLaunchCompletion();

    __shared__ float tile[32][33];
    const int p0 = blockIdx.x * 32;
    const int c0 = blockIdx.y * 32;
    const int tx = threadIdx.x;
    const int ty = threadIdx.y;

#pragma unroll
    for (int i = 0; i < 32; i += 8) {
        tile[ty + i][tx] = in[(size_t)(c0 + ty + i) * (HF * WF) + (p0 + tx)];
    }
    __syncthreads();

    const unsigned long long pol = evict_last_policy();
    const int tid = ty * 32 + tx;
#pragma unroll
    for (int it = 0; it < 2; it++) {
        const int idx = tid + it * 256;
        const int p_local = idx >> 4;
        const int k = idx & 15;
        __half2 h = __floats2half2_rn(tile[2 * k][p_local], tile[2 * k + 1][p_local]);
        unsigned hv = *(unsigned*)&h;
        __half* dst = &g_featTh[(size_t)(p0 + p_local) * CH + c0 + 2 * k];
        asm volatile("st.global.L2::cache_hint.b32 [%0], %1, %2;"
                     :: "l"(dst), "r"(hv), "l"(pol) : "memory");
    }
}

// ---------------------------------------------------------------------------
// Kernel 2: ROI align + 2x2 max subsample (R12 structure, 25.0us proven).
// Grid: (N, 7). Block: 224 threads = 7 pw x 32 c8.
// PDL: prologue (geometry, fractions, offsets) runs before
// cudaGridDependencySynchronize(); the forced LDG.128 batch runs after.
// ---------------------------------------------------------------------------
__global__ __launch_bounds__(NTHR, 3) void roialign_kernel(
    const float* __restrict__ rois,
    const float* __restrict__ img_size,
    float* __restrict__ out)
{
    __shared__ __align__(16) __half s_half[WO * SPITCH];  // 3.7 KB

    const int n   = blockIdx.x;
    const int ph  = blockIdx.y;
    const int tid = threadIdx.x;
    const int pw  = tid >> 5;     // 0..6
    const int c8  = tid & 31;     // 0..31

    // rois/img_size are harness inputs (not produced by the transpose):
    // safe to read before the grid dependency resolves.
    const float4 roi = __ldg((const float4*)rois + n);
    const float Hi = __ldg(img_size);
    const float Wi = __ldg(img_size + 1);
    const float sy_scale = (HF - 1.0f) / (Hi - 1.0f);
    const float sx_scale = (WF - 1.0f) / (Wi - 1.0f);
    const float r0 = roi.x * sy_scale;
    const float r1 = roi.y * sx_scale;
    const float h_step = (roi.z * sy_scale - r0) * (1.0f / (float)HS);
    const float w_step = (roi.w * sx_scale - r1) * (1.0f / (float)WS);

    const float yy0 = ((float)(2 * ph) + 0.5f) * h_step + r0;
    const float yy1 = yy0 + h_step;
    const float xx0 = ((float)(2 * pw) + 0.5f) * w_step + r1;
    const float xx1 = xx0 + w_step;

    const int iy0 = __float2int_rd(yy0);
    const int iy1 = __float2int_rd(yy1);
    const int ix0 = __float2int_rd(xx0);
    const int ix1 = __float2int_rd(xx1);

    const __half2 fy0 = __float2half2_rn(yy0 - (float)iy0);
    const __half2 fy1 = __float2half2_rn(yy1 - (float)iy1);
    const __half2 fx0 = __float2half2_rn(xx0 - (float)ix0);
    const __half2 fx1 = __float2half2_rn(xx1 - (float)ix1);

    const unsigned ru0 = (unsigned)iy0 * ROW_BYTES;
    const unsigned ru1 = (unsigned)iy1 * ROW_BYTES;
    const unsigned rd0 = ru0 + ROW_BYTES;
    const unsigned rd1 = ru1 + ROW_BYTES;
    const unsigned cl0 = (unsigned)ix0 * COL_BYTES;
    const unsigned cl1 = (unsigned)ix1 * COL_BYTES;
    const unsigned cr0 = cl0 + COL_BYTES;
    const unsigned cr1 = cl1 + COL_BYTES;

    const char* fb = (const char*)g_featTh + c8 * 16;
    const unsigned long long pol = evict_last_policy();

    // writeback indices precomputed in the pre-sync window too
    int wc = tid / 7;
    const int wpw = tid - wc * 7;
    float* gp = out + (size_t)n * (CH * HO * WO) + (size_t)wc * (HO * WO)
                    + ph * WO + wpw;

    // --- wait for the transpose grid's memory to be visible ---
    cudaGridDependencySynchronize();

    // --- 16 forced LDG.128s: 64 live registers, back-to-back issue ---
    unsigned v[64];
    LDG128_NC_EL(v +  0, fb + (ru0 + cl0), pol);   // s0 ul
    LDG128_NC_EL(v +  4, fb + (ru0 + cr0), pol);   // s0 ur
    LDG128_NC_EL(v +  8, fb + (rd0 + cl0), pol);   // s0 dl
    LDG128_NC_EL(v + 12, fb + (rd0 + cr0), pol);   // s0 dr
    LDG128_NC_EL(v + 16, fb + (ru0 + cl1), pol);   // s1 ul
    LDG128_NC_EL(v + 20, fb + (ru0 + cr1), pol);   // s1 ur
    LDG128_NC_EL(v + 24, fb + (rd0 + cl1), pol);   // s1 dl
    LDG128_NC_EL(v + 28, fb + (rd0 + cr1), pol);   // s1 dr
    LDG128_NC_EL(v + 32, fb + (ru1 + cl0), pol);   // s2 ul
    LDG128_NC_EL(v + 36, fb + (ru1 + cr0), pol);   // s2 ur
    LDG128_NC_EL(v + 40, fb + (rd1 + cl0), pol);   // s2 dl
    LDG128_NC_EL(v + 44, fb + (rd1 + cr0), pol);   // s2 dr
    LDG128_NC_EL(v + 48, fb + (ru1 + cl1), pol);   // s3 ul
    LDG128_NC_EL(v + 52, fb + (ru1 + cr1), pol);   // s3 ur
    LDG128_NC_EL(v + 56, fb + (rd1 + cl1), pol);   // s3 dl
    LDG128_NC_EL(v + 60, fb + (rd1 + cr1), pol);   // s3 dr

    __half2 best[4];
    const __half2 ninf = __float2half2_rn(-60000.0f);
#pragma unroll
    for (int j = 0; j < 4; j++) best[j] = ninf;

    const __half2 fxs[4] = {fx0, fx1, fx0, fx1};
    const __half2 fys[4] = {fy0, fy0, fy1, fy1};

#pragma unroll
    for (int s = 0; s < 4; s++) {
        const unsigned* pul = v + s * 16 + 0;
        const unsigned* pur = v + s * 16 + 4;
        const unsigned* pdl = v + s * 16 + 8;
        const unsigned* pdr = v + s * 16 + 12;
        const __half2 fx2 = fxs[s];
        const __half2 fy2 = fys[s];
#pragma unroll
        for (int j = 0; j < 4; j++) {
            const __half2 ul = u2h2(pul[j]);
            const __half2 ur = u2h2(pur[j]);
            const __half2 dl = u2h2(pdl[j]);
            const __half2 dr = u2h2(pdr[j]);
            const __half2 t = __hfma2(fx2, __hsub2(ur, ul), ul);
            const __half2 b = __hfma2(fx2, __hsub2(dr, dl), dl);
            const __half2 vv = __hfma2(fy2, __hsub2(b, t), t);
            best[j] = __hmax2(best[j], vv);
        }
    }

    // --- stage results in fp16 smem ---
    *(uint4*)&s_half[pw * SPITCH + c8 * 8] = *(const uint4*)best;
    __syncthreads();

    // --- writeback: fixed pw per thread, c += 32 per iter ---
    {
        const __half* sp = s_half + wpw * SPITCH;
#pragma unroll
        for (int k = 0; k < 8; k++) {
            *gp = __half2float(sp[wc]);
            wc += 32;
            gp += 32 * (HO * WO);
        }
    }
}

extern "C" void kernel_launch(void* const* d_in, const int* in_sizes, int n_in,
                              void* d_out, int out_size) {
    const float* features = (const float*)d_in[0];  // (1, 256, 200, 200)
    const float* rois     = (const float*)d_in[1];  // (512, 4)
    const float* img_size = (const float*)d_in[2];  // (2,)
    float* out = (float*)d_out;                     // (512, 256, 7, 7)

    const int n_rois = in_sizes[1] / 4;

    dim3 tgrid(HF * WF / 32, CH / 32);
    dim3 tblock(32, 8);
    transpose_kernel<<<tgrid, tblock>>>(features);

    // PDL launch: roialign may begin its prologue before the transpose
    // fully drains; cudaGridDependencySynchronize() gates the featT reads.
    cudaLaunchConfig_t cfg = {};
    cfg.gridDim  = dim3((unsigned)n_rois, HO, 1);
    cfg.blockDim = dim3(NTHR, 1, 1);
    cfg.dynamicSmemBytes = 0;
    cfg.stream = 0;
    cudaLaunchAttribute attrs[1];
    attrs[0].id = cudaLaunchAttributeProgrammaticStreamSerialization;
    attrs[0].val.programmaticStreamSerializationAllowed = 1;
    cfg.attrs = attrs;
    cfg.numAttrs = 1;
    cudaLaunchKernelEx(&cfg, roialign_kernel, rois, img_size, out);
}